// round 9
// baseline (speedup 1.0000x reference)
#include <cuda_runtime.h>
#include <cstdint>

// out[b,m,n] = round(alpha * sum_k A[b,m,k]*B[b,n,k]); B=64, M=N=1024, K=128.
// Harness facts: inputs materialized int32, output compared float32,
// ptxas target = sm_103 (NO tcgen05). Tensor work runs on legacy mma.sync.
//
// Kernel 1: pack int32 -> dense int8 scratch (4x traffic cut, L2-resident).
// Kernel 2: persistent CTAs (2/SM), cp.async.cg double-buffered int8 tiles,
//           verified m16n8k32 IMMA core, direct f32 epilogue.

static constexpr int M_DIM = 1024;
static constexpr int N_DIM = 1024;
static constexpr int K_DIM = 128;
static constexpr int BATCH = 64;
static constexpr int TILES = (M_DIM / 128) * (N_DIM / 128) * BATCH;  // 4096
static constexpr int GRID  = 304;   // 2 CTAs/SM on 152 SMs (GB300)
static constexpr float ALPHA_CONST = 0.0078125f;

__device__ int8_t g_a8[(size_t)BATCH * M_DIM * K_DIM];
__device__ int8_t g_b8[(size_t)BATCH * N_DIM * K_DIM];

__device__ __forceinline__ uint32_t pack4(int4 w) {
    uint32_t lo = __byte_perm((uint32_t)w.x, (uint32_t)w.y, 0x0040);
    uint32_t hi = __byte_perm((uint32_t)w.z, (uint32_t)w.w, 0x0040);
    return __byte_perm(lo, hi, 0x5410);
}

// ---------------- kernel 1: int32 -> int8 pack ----------------
__global__ __launch_bounds__(256)
void pack_kernel(const int4* __restrict__ A, const int4* __restrict__ B) {
    size_t t = (size_t)blockIdx.x * 256 + threadIdx.x;   // one 16-value group
    const int4* a = A + t * 4;
    const int4* b = B + t * 4;
    uint4 pa, pb;
    pa.x = pack4(a[0]); pa.y = pack4(a[1]); pa.z = pack4(a[2]); pa.w = pack4(a[3]);
    pb.x = pack4(b[0]); pb.y = pack4(b[1]); pb.z = pack4(b[2]); pb.w = pack4(b[3]);
    reinterpret_cast<uint4*>(g_a8)[t] = pa;
    reinterpret_cast<uint4*>(g_b8)[t] = pb;
}

// ---------------- kernel 2: persistent IMMA GEMM ----------------
__device__ __forceinline__ void cp16(uint32_t dst, const void* src) {
    asm volatile("cp.async.cg.shared.global [%0], [%1], 16;"
                 :: "r"(dst), "l"(src) : "memory");
}

__global__ __launch_bounds__(256, 2)
void gemm_imma_kernel(const float* __restrict__ alpha_p,
                      float* __restrict__ out)
{
    extern __shared__ int8_t smem[];   // 2 buffers x (A 16KB @0 + B 16KB @16384)

    const int tid  = threadIdx.x;
    const int warp = tid >> 5;
    const int lane = tid & 31;

    const float alpha = alpha_p ? *alpha_p : ALPHA_CONST;
    const uint32_t smemS = (uint32_t)__cvta_generic_to_shared(smem);

    const int mBase = (warp >> 2) * 64;   // warp row: 0 or 64
    const int nBase = (warp & 3) * 32;    // warp col: 0,32,64,96

    // ldmatrix x4 lane->matrix map (matches m16n8k32.s8 fragment order)
    const int sub = lane >> 3;
    const int r8 = lane & 7;
    const int ld_row_off = ((sub & 1) << 3) + r8;
    const int ld_col_off = (sub >> 1) << 4;

    const int g  = lane >> 2;      // epilogue: row within 8-row group
    const int tq = lane & 3;       // epilogue: column quad

    auto prefetch = [&](int t, int buf) {
        const int bn = t & 7, bm = (t >> 3) & 7, bz = t >> 6;
        const int8_t* gA = g_a8 + ((size_t)bz * M_DIM + (size_t)bm * 128) * K_DIM;
        const int8_t* gB = g_b8 + ((size_t)bz * N_DIM + (size_t)bn * 128) * K_DIM;
        uint32_t base = smemS + (uint32_t)buf * 32768u;
        #pragma unroll
        for (int i = 0; i < 4; i++) {
            int idx = tid + i * 256;          // 16B chunk, 0..1023
            int row = idx >> 3;
            int chunk = idx & 7;
            uint32_t soff = (uint32_t)row * 128 + (uint32_t)((chunk ^ (row & 7)) << 4);
            cp16(base + soff,          gA + (size_t)idx * 16);
            cp16(base + 16384 + soff,  gB + (size_t)idx * 16);
        }
        asm volatile("cp.async.commit_group;" ::: "memory");
    };

    int tile = blockIdx.x;
    if (tile < TILES) prefetch(tile, 0);

    int it = 0;
    for (; tile < TILES; tile += GRID, it++) {
        asm volatile("cp.async.wait_group 0;" ::: "memory");
        __syncthreads();   // tile data visible to all warps; prev compute done

        const int nt = tile + GRID;
        if (nt < TILES) prefetch(nt, (it + 1) & 1);   // overlaps with compute

        const uint32_t aS = smemS + (uint32_t)(it & 1) * 32768u;
        const uint32_t bS = aS + 16384u;

        int acc[4][4][4];
        #pragma unroll
        for (int mi = 0; mi < 4; mi++)
            #pragma unroll
            for (int ni = 0; ni < 4; ni++)
                #pragma unroll
                for (int r = 0; r < 4; r++)
                    acc[mi][ni][r] = 0;

        #pragma unroll
        for (int kc = 0; kc < 4; kc++) {              // 4 x k32 steps
            const int kcol = kc * 32 + ld_col_off;

            uint32_t a[4][4];
            #pragma unroll
            for (int mi = 0; mi < 4; mi++) {
                int row = mBase + mi * 16 + ld_row_off;
                uint32_t off = (uint32_t)row * 128 + kcol;
                uint32_t addr = aS + (off ^ ((off >> 3) & 0x70));
                asm volatile(
                    "ldmatrix.sync.aligned.m8n8.x4.shared.b16 {%0,%1,%2,%3}, [%4];"
                    : "=r"(a[mi][0]), "=r"(a[mi][1]), "=r"(a[mi][2]), "=r"(a[mi][3])
                    : "r"(addr));
            }

            uint32_t b[2][4];
            #pragma unroll
            for (int nj = 0; nj < 2; nj++) {
                int row = nBase + nj * 16 + ld_row_off;
                uint32_t off = (uint32_t)row * 128 + kcol;
                uint32_t addr = bS + (off ^ ((off >> 3) & 0x70));
                asm volatile(
                    "ldmatrix.sync.aligned.m8n8.x4.shared.b16 {%0,%1,%2,%3}, [%4];"
                    : "=r"(b[nj][0]), "=r"(b[nj][1]), "=r"(b[nj][2]), "=r"(b[nj][3])
                    : "r"(addr));
            }

            #pragma unroll
            for (int mi = 0; mi < 4; mi++) {
                #pragma unroll
                for (int ni = 0; ni < 4; ni++) {
                    const int nj = ni >> 1;
                    const int up = ni & 1;
                    uint32_t b0 = b[nj][up];
                    uint32_t b1 = b[nj][up + 2];
                    asm volatile(
                        "mma.sync.aligned.m16n8k32.row.col.s32.s8.s8.s32 "
                        "{%0,%1,%2,%3}, {%4,%5,%6,%7}, {%8,%9}, {%0,%1,%2,%3};"
                        : "+r"(acc[mi][ni][0]), "+r"(acc[mi][ni][1]),
                          "+r"(acc[mi][ni][2]), "+r"(acc[mi][ni][3])
                        : "r"(a[mi][0]), "r"(a[mi][1]), "r"(a[mi][2]), "r"(a[mi][3]),
                          "r"(b0), "r"(b1));
                }
            }
        }

        // Epilogue: scale, round-half-even (rintf == jnp.round), store FLOAT32.
        const int bn = tile & 7, bm = (tile >> 3) & 7, bz = tile >> 6;
        float* gOut = out + ((size_t)bz * M_DIM + (size_t)bm * 128) * N_DIM
                          + (size_t)bn * 128;

        #pragma unroll
        for (int mi = 0; mi < 4; mi++) {
            #pragma unroll
            for (int ni = 0; ni < 4; ni++) {
                int r0 = mBase + mi * 16 + g;
                int c  = nBase + ni * 8 + tq * 2;
                float2 v0, v1;
                v0.x = rintf((float)acc[mi][ni][0] * alpha);
                v0.y = rintf((float)acc[mi][ni][1] * alpha);
                v1.x = rintf((float)acc[mi][ni][2] * alpha);
                v1.y = rintf((float)acc[mi][ni][3] * alpha);
                *reinterpret_cast<float2*>(gOut + (size_t)r0 * N_DIM + c)       = v0;
                *reinterpret_cast<float2*>(gOut + (size_t)(r0 + 8) * N_DIM + c) = v1;
            }
        }
    }
}

extern "C" void kernel_launch(void* const* d_in, const int* in_sizes, int n_in,
                              void* d_out, int out_size) {
    int i_alpha = -1;
    for (int i = 0; i < n_in; i++)
        if (in_sizes[i] == 1) { i_alpha = i; break; }
    int big[2] = {-1, -1};
    int nb = 0;
    for (int i = 0; i < n_in && nb < 2; i++)
        if (i != i_alpha) big[nb++] = i;
    if (nb < 2) return;

    const int4*  a     = (const int4*)d_in[big[0]];     // int8 values in int32
    const int4*  b     = (const int4*)d_in[big[1]];
    const float* alpha = (i_alpha >= 0) ? (const float*)d_in[i_alpha] : nullptr;
    float*       out   = (float*)d_out;

    // kernel 1: pack (8388608 int32 per tensor / 16 per thread)
    pack_kernel<<<2048, 256>>>(a, b);

    // kernel 2: persistent double-buffered IMMA GEMM (64KB dynamic smem)
    static bool attr_set = false;
    if (!attr_set) {
        cudaFuncSetAttribute(gemm_imma_kernel,
                             cudaFuncAttributeMaxDynamicSharedMemorySize, 65536);
        attr_set = true;
    }
    gemm_imma_kernel<<<GRID, 256, 65536>>>(alpha, out);
}

// round 10
// speedup vs baseline: 1.0591x; 1.0591x over previous
#include <cuda_runtime.h>
#include <cuda_fp16.h>
#include <cstdint>

// out[b,m,n] = round(alpha * sum_k A[b,m,k]*B[b,n,k]); B=64, M=N=1024, K=128.
// Harness facts: inputs int32, output f32, ptxas = sm_103 (no tcgen05).
// Round-9 finding: legacy IMMA rt ~= 57 cyc/mma/SMSP (~158 TOPS) is the wall.
// THIS ROUND: dual-path probe. Pack to int8 AND f16; batches 16-63 run the
// verified IMMA path, batches 0-15 run an HMMA f16 path (exact: int8 values
// and products are exact in f16->f32 accumulation). ncu per-kernel durations
// measure both pipe rates; next round goes all-in on the winner.

static constexpr int M_DIM = 1024;
static constexpr int N_DIM = 1024;
static constexpr int K_DIM = 128;
static constexpr int BATCH = 64;
static constexpr int B_F16 = 16;                       // batches on f16 path
static constexpr int TILES_I8  = 8 * 8 * (BATCH - B_F16);  // 3072
static constexpr int TILES_F16 = 8 * 8 * B_F16;            // 1024
static constexpr int GRID  = 304;   // 2 CTAs/SM on 152 SMs
static constexpr float ALPHA_CONST = 0.0078125f;

__device__ int8_t g_a8[(size_t)BATCH * M_DIM * K_DIM];
__device__ int8_t g_b8[(size_t)BATCH * N_DIM * K_DIM];
__device__ __half g_ah[(size_t)BATCH * M_DIM * K_DIM];
__device__ __half g_bh[(size_t)BATCH * N_DIM * K_DIM];

__device__ __forceinline__ uint32_t pack4(int4 w) {
    uint32_t lo = __byte_perm((uint32_t)w.x, (uint32_t)w.y, 0x0040);
    uint32_t hi = __byte_perm((uint32_t)w.z, (uint32_t)w.w, 0x0040);
    return __byte_perm(lo, hi, 0x5410);
}

__device__ __forceinline__ uint32_t h2pack(int x, int y) {
    __half2 h = __halves2half2(__int2half_rn(x), __int2half_rn(y));
    return *reinterpret_cast<uint32_t*>(&h);
}

// ---------------- kernel 1: int32 -> int8 + f16 pack ----------------
__global__ __launch_bounds__(256)
void pack_kernel(const int4* __restrict__ A, const int4* __restrict__ B) {
    size_t t = (size_t)blockIdx.x * 256 + threadIdx.x;   // one 16-value group
    const size_t elem0 = t * 16;
    const int bz = (int)(elem0 / ((size_t)M_DIM * K_DIM));

    int4 a[4], b[4];
    #pragma unroll
    for (int i = 0; i < 4; i++) { a[i] = A[t * 4 + i]; b[i] = B[t * 4 + i]; }

    if (bz < B_F16) {
        uint4 ha0, ha1, hb0, hb1;
        ha0.x = h2pack(a[0].x, a[0].y); ha0.y = h2pack(a[0].z, a[0].w);
        ha0.z = h2pack(a[1].x, a[1].y); ha0.w = h2pack(a[1].z, a[1].w);
        ha1.x = h2pack(a[2].x, a[2].y); ha1.y = h2pack(a[2].z, a[2].w);
        ha1.z = h2pack(a[3].x, a[3].y); ha1.w = h2pack(a[3].z, a[3].w);
        hb0.x = h2pack(b[0].x, b[0].y); hb0.y = h2pack(b[0].z, b[0].w);
        hb0.z = h2pack(b[1].x, b[1].y); hb0.w = h2pack(b[1].z, b[1].w);
        hb1.x = h2pack(b[2].x, b[2].y); hb1.y = h2pack(b[2].z, b[2].w);
        hb1.z = h2pack(b[3].x, b[3].y); hb1.w = h2pack(b[3].z, b[3].w);
        reinterpret_cast<uint4*>(g_ah)[t * 2 + 0] = ha0;
        reinterpret_cast<uint4*>(g_ah)[t * 2 + 1] = ha1;
        reinterpret_cast<uint4*>(g_bh)[t * 2 + 0] = hb0;
        reinterpret_cast<uint4*>(g_bh)[t * 2 + 1] = hb1;
    } else {
        uint4 pa, pb;
        pa.x = pack4(a[0]); pa.y = pack4(a[1]); pa.z = pack4(a[2]); pa.w = pack4(a[3]);
        pb.x = pack4(b[0]); pb.y = pack4(b[1]); pb.z = pack4(b[2]); pb.w = pack4(b[3]);
        reinterpret_cast<uint4*>(g_a8)[t] = pa;
        reinterpret_cast<uint4*>(g_b8)[t] = pb;
    }
}

__device__ __forceinline__ void cp16(uint32_t dst, const void* src) {
    asm volatile("cp.async.cg.shared.global [%0], [%1], 16;"
                 :: "r"(dst), "l"(src) : "memory");
}

// ---------------- kernel 2: persistent IMMA GEMM (batches 16-63) ----------------
__global__ __launch_bounds__(256, 2)
void gemm_imma_kernel(const float* __restrict__ alpha_p,
                      float* __restrict__ out)
{
    extern __shared__ int8_t smem[];   // 2 x (A 16KB + B 16KB)

    const int tid  = threadIdx.x;
    const int warp = tid >> 5;
    const int lane = tid & 31;

    const float alpha = alpha_p ? *alpha_p : ALPHA_CONST;
    const uint32_t smemS = (uint32_t)__cvta_generic_to_shared(smem);

    const int mBase = (warp >> 2) * 64;
    const int nBase = (warp & 3) * 32;
    const int sub = lane >> 3;
    const int r8 = lane & 7;
    const int ld_row_off = ((sub & 1) << 3) + r8;
    const int ld_col_off = (sub >> 1) << 4;
    const int g  = lane >> 2;
    const int tq = lane & 3;

    auto prefetch = [&](int t, int buf) {
        const int bn = t & 7, bm = (t >> 3) & 7, bz = (t >> 6) + B_F16;
        const int8_t* gA = g_a8 + ((size_t)bz * M_DIM + (size_t)bm * 128) * K_DIM;
        const int8_t* gB = g_b8 + ((size_t)bz * N_DIM + (size_t)bn * 128) * K_DIM;
        uint32_t base = smemS + (uint32_t)buf * 32768u;
        #pragma unroll
        for (int i = 0; i < 4; i++) {
            int idx = tid + i * 256;
            int row = idx >> 3;
            int chunk = idx & 7;
            uint32_t soff = (uint32_t)row * 128 + (uint32_t)((chunk ^ (row & 7)) << 4);
            cp16(base + soff,         gA + (size_t)idx * 16);
            cp16(base + 16384 + soff, gB + (size_t)idx * 16);
        }
        asm volatile("cp.async.commit_group;" ::: "memory");
    };

    int tile = blockIdx.x;
    if (tile < TILES_I8) prefetch(tile, 0);

    int it = 0;
    for (; tile < TILES_I8; tile += GRID, it++) {
        asm volatile("cp.async.wait_group 0;" ::: "memory");
        __syncthreads();

        const int nt = tile + GRID;
        if (nt < TILES_I8) prefetch(nt, (it + 1) & 1);

        const uint32_t aS = smemS + (uint32_t)(it & 1) * 32768u;
        const uint32_t bS = aS + 16384u;

        int acc[4][4][4];
        #pragma unroll
        for (int mi = 0; mi < 4; mi++)
            #pragma unroll
            for (int ni = 0; ni < 4; ni++)
                #pragma unroll
                for (int r = 0; r < 4; r++)
                    acc[mi][ni][r] = 0;

        #pragma unroll
        for (int kc = 0; kc < 4; kc++) {
            const int kcol = kc * 32 + ld_col_off;
            uint32_t a[4][4];
            #pragma unroll
            for (int mi = 0; mi < 4; mi++) {
                int row = mBase + mi * 16 + ld_row_off;
                uint32_t off = (uint32_t)row * 128 + kcol;
                uint32_t addr = aS + (off ^ ((off >> 3) & 0x70));
                asm volatile(
                    "ldmatrix.sync.aligned.m8n8.x4.shared.b16 {%0,%1,%2,%3}, [%4];"
                    : "=r"(a[mi][0]), "=r"(a[mi][1]), "=r"(a[mi][2]), "=r"(a[mi][3])
                    : "r"(addr));
            }
            uint32_t b[2][4];
            #pragma unroll
            for (int nj = 0; nj < 2; nj++) {
                int row = nBase + nj * 16 + ld_row_off;
                uint32_t off = (uint32_t)row * 128 + kcol;
                uint32_t addr = bS + (off ^ ((off >> 3) & 0x70));
                asm volatile(
                    "ldmatrix.sync.aligned.m8n8.x4.shared.b16 {%0,%1,%2,%3}, [%4];"
                    : "=r"(b[nj][0]), "=r"(b[nj][1]), "=r"(b[nj][2]), "=r"(b[nj][3])
                    : "r"(addr));
            }
            #pragma unroll
            for (int mi = 0; mi < 4; mi++) {
                #pragma unroll
                for (int ni = 0; ni < 4; ni++) {
                    const int nj = ni >> 1;
                    const int up = ni & 1;
                    asm volatile(
                        "mma.sync.aligned.m16n8k32.row.col.s32.s8.s8.s32 "
                        "{%0,%1,%2,%3}, {%4,%5,%6,%7}, {%8,%9}, {%0,%1,%2,%3};"
                        : "+r"(acc[mi][ni][0]), "+r"(acc[mi][ni][1]),
                          "+r"(acc[mi][ni][2]), "+r"(acc[mi][ni][3])
                        : "r"(a[mi][0]), "r"(a[mi][1]), "r"(a[mi][2]), "r"(a[mi][3]),
                          "r"(b[nj][up]), "r"(b[nj][up + 2]));
                }
            }
        }

        const int bn = tile & 7, bm = (tile >> 3) & 7, bz = (tile >> 6) + B_F16;
        float* gOut = out + ((size_t)bz * M_DIM + (size_t)bm * 128) * N_DIM
                          + (size_t)bn * 128;
        #pragma unroll
        for (int mi = 0; mi < 4; mi++) {
            #pragma unroll
            for (int ni = 0; ni < 4; ni++) {
                int r0 = mBase + mi * 16 + g;
                int c  = nBase + ni * 8 + tq * 2;
                float2 v0, v1;
                v0.x = rintf((float)acc[mi][ni][0] * alpha);
                v0.y = rintf((float)acc[mi][ni][1] * alpha);
                v1.x = rintf((float)acc[mi][ni][2] * alpha);
                v1.y = rintf((float)acc[mi][ni][3] * alpha);
                *reinterpret_cast<float2*>(gOut + (size_t)r0 * N_DIM + c)       = v0;
                *reinterpret_cast<float2*>(gOut + (size_t)(r0 + 8) * N_DIM + c) = v1;
            }
        }
    }
}

// ---------------- kernel 3: persistent HMMA f16 GEMM (batches 0-15) ----------------
// smem tile: 128 rows x 256B (128 f16). 16B chunks, chunk' = chunk ^ (row&7).
// Single 64KB buffer (A @0, B @32768), 2 CTAs/SM overlap loads with compute.
__global__ __launch_bounds__(256, 2)
void gemm_hmma_kernel(const float* __restrict__ alpha_p,
                      float* __restrict__ out)
{
    extern __shared__ int8_t smem[];

    const int tid  = threadIdx.x;
    const int warp = tid >> 5;
    const int lane = tid & 31;

    const float alpha = alpha_p ? *alpha_p : ALPHA_CONST;
    const uint32_t smemS = (uint32_t)__cvta_generic_to_shared(smem);

    const int mBase = (warp >> 2) * 64;
    const int nBase = (warp & 3) * 32;
    const int sub = lane >> 3;
    const int r8 = lane & 7;
    const int ld_row_off = ((sub & 1) << 3) + r8;
    const int ld_chunk   = sub >> 1;               // 0 or 1 within k16 step
    const int g  = lane >> 2;
    const int tq = lane & 3;

    auto prefetch = [&](int t) {
        const int bn = t & 7, bm = (t >> 3) & 7, bz = t >> 6;
        const __half* gA = g_ah + ((size_t)bz * M_DIM + (size_t)bm * 128) * K_DIM;
        const __half* gB = g_bh + ((size_t)bz * N_DIM + (size_t)bn * 128) * K_DIM;
        #pragma unroll
        for (int i = 0; i < 8; i++) {
            int idx = tid + i * 256;              // 16B chunk, 0..2047
            int row = idx >> 4;
            int c   = idx & 15;
            uint32_t soff = (uint32_t)row * 256 + (uint32_t)((c ^ (row & 7)) << 4);
            cp16(smemS + soff,          gA + (size_t)idx * 8);
            cp16(smemS + 32768 + soff,  gB + (size_t)idx * 8);
        }
        asm volatile("cp.async.commit_group;" ::: "memory");
    };

    int tile = blockIdx.x;
    if (tile < TILES_F16) prefetch(tile);

    for (; tile < TILES_F16; tile += GRID) {
        asm volatile("cp.async.wait_group 0;" ::: "memory");
        __syncthreads();

        float acc[4][4][4];
        #pragma unroll
        for (int mi = 0; mi < 4; mi++)
            #pragma unroll
            for (int ni = 0; ni < 4; ni++)
                #pragma unroll
                for (int r = 0; r < 4; r++)
                    acc[mi][ni][r] = 0.0f;

        #pragma unroll
        for (int kc = 0; kc < 8; kc++) {          // 8 x k16 steps
            const int chunk = kc * 2 + ld_chunk;

            uint32_t a[4][4];
            #pragma unroll
            for (int mi = 0; mi < 4; mi++) {
                int row = mBase + mi * 16 + ld_row_off;
                uint32_t addr = smemS + (uint32_t)row * 256
                              + (uint32_t)((chunk ^ (row & 7)) << 4);
                asm volatile(
                    "ldmatrix.sync.aligned.m8n8.x4.shared.b16 {%0,%1,%2,%3}, [%4];"
                    : "=r"(a[mi][0]), "=r"(a[mi][1]), "=r"(a[mi][2]), "=r"(a[mi][3])
                    : "r"(addr));
            }
            uint32_t b[2][4];
            #pragma unroll
            for (int nj = 0; nj < 2; nj++) {
                int row = nBase + nj * 16 + ld_row_off;
                uint32_t addr = smemS + 32768u + (uint32_t)row * 256
                              + (uint32_t)((chunk ^ (row & 7)) << 4);
                asm volatile(
                    "ldmatrix.sync.aligned.m8n8.x4.shared.b16 {%0,%1,%2,%3}, [%4];"
                    : "=r"(b[nj][0]), "=r"(b[nj][1]), "=r"(b[nj][2]), "=r"(b[nj][3])
                    : "r"(addr));
            }
            #pragma unroll
            for (int mi = 0; mi < 4; mi++) {
                #pragma unroll
                for (int ni = 0; ni < 4; ni++) {
                    const int nj = ni >> 1;
                    const int up = ni & 1;
                    asm volatile(
                        "mma.sync.aligned.m16n8k16.row.col.f32.f16.f16.f32 "
                        "{%0,%1,%2,%3}, {%4,%5,%6,%7}, {%8,%9}, {%0,%1,%2,%3};"
                        : "+f"(acc[mi][ni][0]), "+f"(acc[mi][ni][1]),
                          "+f"(acc[mi][ni][2]), "+f"(acc[mi][ni][3])
                        : "r"(a[mi][0]), "r"(a[mi][1]), "r"(a[mi][2]), "r"(a[mi][3]),
                          "r"(b[nj][up]), "r"(b[nj][up + 2]));
                }
            }
        }

        __syncthreads();                           // tile fully consumed
        const int nt = tile + GRID;
        if (nt < TILES_F16) prefetch(nt);          // overlaps epilogue

        const int bn = tile & 7, bm = (tile >> 3) & 7, bz = tile >> 6;
        float* gOut = out + ((size_t)bz * M_DIM + (size_t)bm * 128) * N_DIM
                          + (size_t)bn * 128;
        #pragma unroll
        for (int mi = 0; mi < 4; mi++) {
            #pragma unroll
            for (int ni = 0; ni < 4; ni++) {
                int r0 = mBase + mi * 16 + g;
                int c  = nBase + ni * 8 + tq * 2;
                float2 v0, v1;
                v0.x = rintf(acc[mi][ni][0] * alpha);
                v0.y = rintf(acc[mi][ni][1] * alpha);
                v1.x = rintf(acc[mi][ni][2] * alpha);
                v1.y = rintf(acc[mi][ni][3] * alpha);
                *reinterpret_cast<float2*>(gOut + (size_t)r0 * N_DIM + c)       = v0;
                *reinterpret_cast<float2*>(gOut + (size_t)(r0 + 8) * N_DIM + c) = v1;
            }
        }
    }
}

extern "C" void kernel_launch(void* const* d_in, const int* in_sizes, int n_in,
                              void* d_out, int out_size) {
    int i_alpha = -1;
    for (int i = 0; i < n_in; i++)
        if (in_sizes[i] == 1) { i_alpha = i; break; }
    int big[2] = {-1, -1};
    int nb = 0;
    for (int i = 0; i < n_in && nb < 2; i++)
        if (i != i_alpha) big[nb++] = i;
    if (nb < 2) return;

    const int4*  a     = (const int4*)d_in[big[0]];
    const int4*  b     = (const int4*)d_in[big[1]];
    const float* alpha = (i_alpha >= 0) ? (const float*)d_in[i_alpha] : nullptr;
    float*       out   = (float*)d_out;

    static bool attr_set = false;
    if (!attr_set) {
        cudaFuncSetAttribute(gemm_imma_kernel,
                             cudaFuncAttributeMaxDynamicSharedMemorySize, 65536);
        cudaFuncSetAttribute(gemm_hmma_kernel,
                             cudaFuncAttributeMaxDynamicSharedMemorySize, 65536);
        attr_set = true;
    }

    pack_kernel<<<2048, 256>>>(a, b);
    gemm_imma_kernel<<<GRID, 256, 65536>>>(alpha, out);   // batches 16-63
    gemm_hmma_kernel<<<GRID, 256, 65536>>>(alpha, out);   // batches 0-15
}

// round 11
// speedup vs baseline: 1.4678x; 1.3859x over previous
#include <cuda_runtime.h>
#include <cuda_fp16.h>
#include <cstdint>

// out[b,m,n] = round(alpha * sum_k A[b,m,k]*B[b,n,k]); B=64, M=N=1024, K=128.
// Harness facts: inputs materialized int32, output compared float32,
// ptxas = sm_103 (no tcgen05).
// Round-10 probe: legacy HMMA f16 ~= 23.7 ns/tile vs IMMA 32.8 ns/tile
// => all batches on the f16 path. Exact: int8 values/products exact in
// f16 -> f32 accumulation (sums < 2^24).
//
// Kernel 1: pack int32 -> f16 scratch.
// Kernel 2: persistent HMMA m16n8k16 GEMM (verified round-10 structure),
//           2 CTAs/SM, cp.async tile loads, f32 epilogue with rintf.

static constexpr int M_DIM = 1024;
static constexpr int N_DIM = 1024;
static constexpr int K_DIM = 128;
static constexpr int BATCH = 64;
static constexpr int TILES = 8 * 8 * BATCH;   // 4096
static constexpr int GRID  = 304;             // 2 CTAs/SM on 152 SMs
static constexpr float ALPHA_CONST = 0.0078125f;

__device__ __half g_ah[(size_t)BATCH * M_DIM * K_DIM];
__device__ __half g_bh[(size_t)BATCH * N_DIM * K_DIM];

__device__ __forceinline__ uint32_t h2pack(int x, int y) {
    __half2 h = __halves2half2(__int2half_rn(x), __int2half_rn(y));
    return *reinterpret_cast<uint32_t*>(&h);
}

// ---------------- kernel 1: int32 -> f16 pack ----------------
__global__ __launch_bounds__(256)
void pack_kernel(const int4* __restrict__ A, const int4* __restrict__ B) {
    size_t t = (size_t)blockIdx.x * 256 + threadIdx.x;   // one 16-value group

    int4 a[4], b[4];
    #pragma unroll
    for (int i = 0; i < 4; i++) { a[i] = A[t * 4 + i]; b[i] = B[t * 4 + i]; }

    uint4 ha0, ha1, hb0, hb1;
    ha0.x = h2pack(a[0].x, a[0].y); ha0.y = h2pack(a[0].z, a[0].w);
    ha0.z = h2pack(a[1].x, a[1].y); ha0.w = h2pack(a[1].z, a[1].w);
    ha1.x = h2pack(a[2].x, a[2].y); ha1.y = h2pack(a[2].z, a[2].w);
    ha1.z = h2pack(a[3].x, a[3].y); ha1.w = h2pack(a[3].z, a[3].w);
    hb0.x = h2pack(b[0].x, b[0].y); hb0.y = h2pack(b[0].z, b[0].w);
    hb0.z = h2pack(b[1].x, b[1].y); hb0.w = h2pack(b[1].z, b[1].w);
    hb1.x = h2pack(b[2].x, b[2].y); hb1.y = h2pack(b[2].z, b[2].w);
    hb1.z = h2pack(b[3].x, b[3].y); hb1.w = h2pack(b[3].z, b[3].w);
    reinterpret_cast<uint4*>(g_ah)[t * 2 + 0] = ha0;
    reinterpret_cast<uint4*>(g_ah)[t * 2 + 1] = ha1;
    reinterpret_cast<uint4*>(g_bh)[t * 2 + 0] = hb0;
    reinterpret_cast<uint4*>(g_bh)[t * 2 + 1] = hb1;
}

__device__ __forceinline__ void cp16(uint32_t dst, const void* src) {
    asm volatile("cp.async.cg.shared.global [%0], [%1], 16;"
                 :: "r"(dst), "l"(src) : "memory");
}

// ---------------- kernel 2: persistent HMMA f16 GEMM ----------------
// smem tile: 128 rows x 256B (128 f16) per operand; A @0, B @32768 (64KB).
// 16B chunks swizzled chunk^ (row&7) -> conflict-free ldmatrix.
__global__ __launch_bounds__(256, 2)
void gemm_hmma_kernel(const float* __restrict__ alpha_p,
                      float* __restrict__ out)
{
    extern __shared__ int8_t smem[];

    const int tid  = threadIdx.x;
    const int warp = tid >> 5;
    const int lane = tid & 31;

    const float alpha = alpha_p ? *alpha_p : ALPHA_CONST;
    const uint32_t smemS = (uint32_t)__cvta_generic_to_shared(smem);

    const int mBase = (warp >> 2) * 64;   // warp row: 0 or 64
    const int nBase = (warp & 3) * 32;    // warp col: 0,32,64,96
    const int sub = lane >> 3;
    const int r8 = lane & 7;
    const int ld_row_off = ((sub & 1) << 3) + r8;
    const int ld_chunk   = sub >> 1;      // 0 or 1 within a k16 step
    const int g  = lane >> 2;
    const int tq = lane & 3;

    auto prefetch = [&](int t) {
        const int bn = t & 7, bm = (t >> 3) & 7, bz = t >> 6;
        const __half* gA = g_ah + ((size_t)bz * M_DIM + (size_t)bm * 128) * K_DIM;
        const __half* gB = g_bh + ((size_t)bz * N_DIM + (size_t)bn * 128) * K_DIM;
        #pragma unroll
        for (int i = 0; i < 8; i++) {
            int idx = tid + i * 256;              // 16B chunk, 0..2047
            int row = idx >> 4;
            int c   = idx & 15;
            uint32_t soff = (uint32_t)row * 256 + (uint32_t)((c ^ (row & 7)) << 4);
            cp16(smemS + soff,          gA + (size_t)idx * 8);
            cp16(smemS + 32768 + soff,  gB + (size_t)idx * 8);
        }
        asm volatile("cp.async.commit_group;" ::: "memory");
    };

    int tile = blockIdx.x;
    if (tile < TILES) prefetch(tile);

    for (; tile < TILES; tile += GRID) {
        asm volatile("cp.async.wait_group 0;" ::: "memory");
        __syncthreads();

        float acc[4][4][4];
        #pragma unroll
        for (int mi = 0; mi < 4; mi++)
            #pragma unroll
            for (int ni = 0; ni < 4; ni++)
                #pragma unroll
                for (int r = 0; r < 4; r++)
                    acc[mi][ni][r] = 0.0f;

        #pragma unroll
        for (int kc = 0; kc < 8; kc++) {          // 8 x k16 steps
            const int chunk = kc * 2 + ld_chunk;

            uint32_t a[4][4];
            #pragma unroll
            for (int mi = 0; mi < 4; mi++) {
                int row = mBase + mi * 16 + ld_row_off;
                uint32_t addr = smemS + (uint32_t)row * 256
                              + (uint32_t)((chunk ^ (row & 7)) << 4);
                asm volatile(
                    "ldmatrix.sync.aligned.m8n8.x4.shared.b16 {%0,%1,%2,%3}, [%4];"
                    : "=r"(a[mi][0]), "=r"(a[mi][1]), "=r"(a[mi][2]), "=r"(a[mi][3])
                    : "r"(addr));
            }
            uint32_t b[2][4];
            #pragma unroll
            for (int nj = 0; nj < 2; nj++) {
                int row = nBase + nj * 16 + ld_row_off;
                uint32_t addr = smemS + 32768u + (uint32_t)row * 256
                              + (uint32_t)((chunk ^ (row & 7)) << 4);
                asm volatile(
                    "ldmatrix.sync.aligned.m8n8.x4.shared.b16 {%0,%1,%2,%3}, [%4];"
                    : "=r"(b[nj][0]), "=r"(b[nj][1]), "=r"(b[nj][2]), "=r"(b[nj][3])
                    : "r"(addr));
            }
            #pragma unroll
            for (int mi = 0; mi < 4; mi++) {
                #pragma unroll
                for (int ni = 0; ni < 4; ni++) {
                    const int nj = ni >> 1;
                    const int up = ni & 1;
                    asm volatile(
                        "mma.sync.aligned.m16n8k16.row.col.f32.f16.f16.f32 "
                        "{%0,%1,%2,%3}, {%4,%5,%6,%7}, {%8,%9}, {%0,%1,%2,%3};"
                        : "+f"(acc[mi][ni][0]), "+f"(acc[mi][ni][1]),
                          "+f"(acc[mi][ni][2]), "+f"(acc[mi][ni][3])
                        : "r"(a[mi][0]), "r"(a[mi][1]), "r"(a[mi][2]), "r"(a[mi][3]),
                          "r"(b[nj][up]), "r"(b[nj][up + 2]));
                }
            }
        }

        __syncthreads();                           // tile fully consumed
        const int nt = tile + GRID;
        if (nt < TILES) prefetch(nt);              // overlaps epilogue

        const int bn = tile & 7, bm = (tile >> 3) & 7, bz = tile >> 6;
        float* gOut = out + ((size_t)bz * M_DIM + (size_t)bm * 128) * N_DIM
                          + (size_t)bn * 128;
        #pragma unroll
        for (int mi = 0; mi < 4; mi++) {
            #pragma unroll
            for (int ni = 0; ni < 4; ni++) {
                int r0 = mBase + mi * 16 + g;
                int c  = nBase + ni * 8 + tq * 2;
                float2 v0, v1;
                v0.x = rintf(acc[mi][ni][0] * alpha);
                v0.y = rintf(acc[mi][ni][1] * alpha);
                v1.x = rintf(acc[mi][ni][2] * alpha);
                v1.y = rintf(acc[mi][ni][3] * alpha);
                *reinterpret_cast<float2*>(gOut + (size_t)r0 * N_DIM + c)       = v0;
                *reinterpret_cast<float2*>(gOut + (size_t)(r0 + 8) * N_DIM + c) = v1;
            }
        }
    }
}

extern "C" void kernel_launch(void* const* d_in, const int* in_sizes, int n_in,
                              void* d_out, int out_size) {
    int i_alpha = -1;
    for (int i = 0; i < n_in; i++)
        if (in_sizes[i] == 1) { i_alpha = i; break; }
    int big[2] = {-1, -1};
    int nb = 0;
    for (int i = 0; i < n_in && nb < 2; i++)
        if (i != i_alpha) big[nb++] = i;
    if (nb < 2) return;

    const int4*  a     = (const int4*)d_in[big[0]];
    const int4*  b     = (const int4*)d_in[big[1]];
    const float* alpha = (i_alpha >= 0) ? (const float*)d_in[i_alpha] : nullptr;
    float*       out   = (float*)d_out;

    static bool attr_set = false;
    if (!attr_set) {
        cudaFuncSetAttribute(gemm_hmma_kernel,
                             cudaFuncAttributeMaxDynamicSharedMemorySize, 65536);
        attr_set = true;
    }

    pack_kernel<<<2048, 256>>>(a, b);                 // int32 -> f16
    gemm_hmma_kernel<<<GRID, 256, 65536>>>(alpha, out);
}

// round 12
// speedup vs baseline: 1.4974x; 1.0202x over previous
#include <cuda_runtime.h>
#include <cuda_fp16.h>
#include <cstdint>

// out[b,m,n] = round(alpha * sum_k A[b,m,k]*B[b,n,k]); B=64, M=N=1024, K=128.
// Harness facts: inputs materialized int32, output compared float32,
// ptxas = sm_103 (no tcgen05). HMMA f16 path (exact for int8 data).
//
// Round-12: software-pipelined GEMM. Each 128x128 tile is loaded in 4 k32
// stages (16KB each: A 8KB + B 8KB), ring of 4 slots, cp.async pipeline
// 3 stages deep across tile boundaries. wait_group 2 -> sync -> compute
// stage g -> issue stage g+3. One commit group per stage (unconditional).

static constexpr int M_DIM = 1024;
static constexpr int N_DIM = 1024;
static constexpr int K_DIM = 128;
static constexpr int BATCH = 64;
static constexpr int TILES = 8 * 8 * BATCH;   // 4096
static constexpr int GRID  = 304;             // 2 CTAs/SM on 152 SMs
static constexpr float ALPHA_CONST = 0.0078125f;

static constexpr uint32_t SLOT_BYTES = 16384;   // A 8KB @0, B 8KB @8192
static constexpr uint32_t B_OFF      = 8192;

__device__ __half g_ah[(size_t)BATCH * M_DIM * K_DIM];
__device__ __half g_bh[(size_t)BATCH * N_DIM * K_DIM];

__device__ __forceinline__ uint32_t h2pack(int x, int y) {
    __half2 h = __halves2half2(__int2half_rn(x), __int2half_rn(y));
    return *reinterpret_cast<uint32_t*>(&h);
}

// ---------------- kernel 1: int32 -> f16 pack ----------------
__global__ __launch_bounds__(256)
void pack_kernel(const int4* __restrict__ A, const int4* __restrict__ B) {
    size_t t = (size_t)blockIdx.x * 256 + threadIdx.x;   // one 16-value group

    int4 a[4], b[4];
    #pragma unroll
    for (int i = 0; i < 4; i++) { a[i] = A[t * 4 + i]; b[i] = B[t * 4 + i]; }

    uint4 ha0, ha1, hb0, hb1;
    ha0.x = h2pack(a[0].x, a[0].y); ha0.y = h2pack(a[0].z, a[0].w);
    ha0.z = h2pack(a[1].x, a[1].y); ha0.w = h2pack(a[1].z, a[1].w);
    ha1.x = h2pack(a[2].x, a[2].y); ha1.y = h2pack(a[2].z, a[2].w);
    ha1.z = h2pack(a[3].x, a[3].y); ha1.w = h2pack(a[3].z, a[3].w);
    hb0.x = h2pack(b[0].x, b[0].y); hb0.y = h2pack(b[0].z, b[0].w);
    hb0.z = h2pack(b[1].x, b[1].y); hb0.w = h2pack(b[1].z, b[1].w);
    hb1.x = h2pack(b[2].x, b[2].y); hb1.y = h2pack(b[2].z, b[2].w);
    hb1.z = h2pack(b[3].x, b[3].y); hb1.w = h2pack(b[3].z, b[3].w);
    reinterpret_cast<uint4*>(g_ah)[t * 2 + 0] = ha0;
    reinterpret_cast<uint4*>(g_ah)[t * 2 + 1] = ha1;
    reinterpret_cast<uint4*>(g_bh)[t * 2 + 0] = hb0;
    reinterpret_cast<uint4*>(g_bh)[t * 2 + 1] = hb1;
}

__device__ __forceinline__ void cp16(uint32_t dst, const void* src) {
    asm volatile("cp.async.cg.shared.global [%0], [%1], 16;"
                 :: "r"(dst), "l"(src) : "memory");
}

// ---------------- kernel 2: pipelined persistent HMMA GEMM ----------------
// Stage slot: 128 rows x 64B per operand. 16B chunk swizzle: c ^= (row>>1)&3
// -> conflict-free for both STS and 8-row ldmatrix phases.
__global__ __launch_bounds__(256, 2)
void gemm_hmma_kernel(const float* __restrict__ alpha_p,
                      float* __restrict__ out)
{
    extern __shared__ int8_t smem[];   // 4 slots x 16KB

    const int tid  = threadIdx.x;
    const int warp = tid >> 5;
    const int lane = tid & 31;
    const int bid  = blockIdx.x;

    const float alpha = alpha_p ? *alpha_p : ALPHA_CONST;
    const uint32_t smemS = (uint32_t)__cvta_generic_to_shared(smem);

    const int mBase = (warp >> 2) * 64;   // warp row: 0 or 64
    const int nBase = (warp & 3) * 32;    // warp col: 0,32,64,96
    const int sub = lane >> 3;
    const int r8 = lane & 7;
    const int ld_row_off = ((sub & 1) << 3) + r8;
    const int ld_chunk   = sub >> 1;      // 0/1: which 16B within a k16 step
    const int g  = lane >> 2;
    const int tq = lane & 3;

    // issue loads for global stage gs (tile = bid + (gs>>2)*GRID, kc = gs&3);
    // ALWAYS commits a group so wait_group counting stays uniform.
    auto load_stage = [&](int gs) {
        const int t = bid + (gs >> 2) * GRID;
        if (t < TILES) {
            const int kc = gs & 3;
            const int bn = t & 7, bm = (t >> 3) & 7, bz = t >> 6;
            const int8_t* gA = reinterpret_cast<const int8_t*>(g_ah)
                + ((size_t)bz * M_DIM + (size_t)bm * 128) * (K_DIM * 2);
            const int8_t* gB = reinterpret_cast<const int8_t*>(g_bh)
                + ((size_t)bz * N_DIM + (size_t)bn * 128) * (K_DIM * 2);
            const uint32_t slot = smemS + (uint32_t)(gs & 3) * SLOT_BYTES;
            #pragma unroll
            for (int i = 0; i < 2; i++) {
                int idx = tid + i * 256;          // 0..511: row*4 + chunk
                int row = idx >> 2;
                int c   = idx & 3;
                uint32_t soff = (uint32_t)row * 64
                              + (uint32_t)((c ^ ((row >> 1) & 3)) << 4);
                const size_t goff = (size_t)row * 256 + (size_t)kc * 64 + (size_t)c * 16;
                cp16(slot + soff,         gA + goff);
                cp16(slot + B_OFF + soff, gB + goff);
            }
        }
        asm volatile("cp.async.commit_group;" ::: "memory");
    };

    const int ntiles = (TILES - bid + GRID - 1) / GRID;
    const int total_stages = ntiles * 4;

    load_stage(0);
    load_stage(1);
    load_stage(2);

    float acc[4][4][4];

    for (int gs = 0; gs < total_stages; gs++) {
        asm volatile("cp.async.wait_group 2;" ::: "memory");
        __syncthreads();   // stage data visible; prior slot reads finished

        if ((gs & 3) == 0) {
            #pragma unroll
            for (int mi = 0; mi < 4; mi++)
                #pragma unroll
                for (int ni = 0; ni < 4; ni++)
                    #pragma unroll
                    for (int r = 0; r < 4; r++)
                        acc[mi][ni][r] = 0.0f;
        }

        const uint32_t slot = smemS + (uint32_t)(gs & 3) * SLOT_BYTES;

        #pragma unroll
        for (int kk2 = 0; kk2 < 2; kk2++) {       // 2 x k16 per stage
            const int c = kk2 * 2 + ld_chunk;

            uint32_t a[4][4];
            #pragma unroll
            for (int mi = 0; mi < 4; mi++) {
                int row = mBase + mi * 16 + ld_row_off;
                uint32_t addr = slot + (uint32_t)row * 64
                              + (uint32_t)((c ^ ((row >> 1) & 3)) << 4);
                asm volatile(
                    "ldmatrix.sync.aligned.m8n8.x4.shared.b16 {%0,%1,%2,%3}, [%4];"
                    : "=r"(a[mi][0]), "=r"(a[mi][1]), "=r"(a[mi][2]), "=r"(a[mi][3])
                    : "r"(addr));
            }
            uint32_t b[2][4];
            #pragma unroll
            for (int nj = 0; nj < 2; nj++) {
                int row = nBase + nj * 16 + ld_row_off;
                uint32_t addr = slot + B_OFF + (uint32_t)row * 64
                              + (uint32_t)((c ^ ((row >> 1) & 3)) << 4);
                asm volatile(
                    "ldmatrix.sync.aligned.m8n8.x4.shared.b16 {%0,%1,%2,%3}, [%4];"
                    : "=r"(b[nj][0]), "=r"(b[nj][1]), "=r"(b[nj][2]), "=r"(b[nj][3])
                    : "r"(addr));
            }
            #pragma unroll
            for (int mi = 0; mi < 4; mi++) {
                #pragma unroll
                for (int ni = 0; ni < 4; ni++) {
                    const int nj = ni >> 1;
                    const int up = ni & 1;
                    asm volatile(
                        "mma.sync.aligned.m16n8k16.row.col.f32.f16.f16.f32 "
                        "{%0,%1,%2,%3}, {%4,%5,%6,%7}, {%8,%9}, {%0,%1,%2,%3};"
                        : "+f"(acc[mi][ni][0]), "+f"(acc[mi][ni][1]),
                          "+f"(acc[mi][ni][2]), "+f"(acc[mi][ni][3])
                        : "r"(a[mi][0]), "r"(a[mi][1]), "r"(a[mi][2]), "r"(a[mi][3]),
                          "r"(b[nj][up]), "r"(b[nj][up + 2]));
                }
            }
        }

        load_stage(gs + 3);   // refill pipeline (slot (gs+3)&3 is free)

        if ((gs & 3) == 3) {
            const int t = bid + (gs >> 2) * GRID;
            const int bn = t & 7, bm = (t >> 3) & 7, bz = t >> 6;
            float* gOut = out + ((size_t)bz * M_DIM + (size_t)bm * 128) * N_DIM
                              + (size_t)bn * 128;
            #pragma unroll
            for (int mi = 0; mi < 4; mi++) {
                #pragma unroll
                for (int ni = 0; ni < 4; ni++) {
                    int r0 = mBase + mi * 16 + g;
                    int c2 = nBase + ni * 8 + tq * 2;
                    float2 v0, v1;
                    v0.x = rintf(acc[mi][ni][0] * alpha);
                    v0.y = rintf(acc[mi][ni][1] * alpha);
                    v1.x = rintf(acc[mi][ni][2] * alpha);
                    v1.y = rintf(acc[mi][ni][3] * alpha);
                    *reinterpret_cast<float2*>(gOut + (size_t)r0 * N_DIM + c2)       = v0;
                    *reinterpret_cast<float2*>(gOut + (size_t)(r0 + 8) * N_DIM + c2) = v1;
                }
            }
        }
    }
}

extern "C" void kernel_launch(void* const* d_in, const int* in_sizes, int n_in,
                              void* d_out, int out_size) {
    int i_alpha = -1;
    for (int i = 0; i < n_in; i++)
        if (in_sizes[i] == 1) { i_alpha = i; break; }
    int big[2] = {-1, -1};
    int nb = 0;
    for (int i = 0; i < n_in && nb < 2; i++)
        if (i != i_alpha) big[nb++] = i;
    if (nb < 2) return;

    const int4*  a     = (const int4*)d_in[big[0]];
    const int4*  b     = (const int4*)d_in[big[1]];
    const float* alpha = (i_alpha >= 0) ? (const float*)d_in[i_alpha] : nullptr;
    float*       out   = (float*)d_out;

    static bool attr_set = false;
    if (!attr_set) {
        cudaFuncSetAttribute(gemm_hmma_kernel,
                             cudaFuncAttributeMaxDynamicSharedMemorySize, 65536);
        attr_set = true;
    }

    pack_kernel<<<2048, 256>>>(a, b);                    // int32 -> f16
    gemm_hmma_kernel<<<GRID, 256, 65536>>>(alpha, out);  // pipelined GEMM
}